// round 8
// baseline (speedup 1.0000x reference)
#include <cuda_runtime.h>
#include <cuda_bf16.h>
#include <cstdint>

// Problem constants
#define BB 16
#define AA 8400
#define GG 64
#define CC 80
#define KK 10
#define CAP 512            // max positive-align candidates per (b,g); worst-case n ~325

#define EPSF 1e-9f
#define CPI  0.4052847345693511f   // 4 / pi^2

// Output layout (flattened tuple, float32)
#define OFF0 0
#define OFF1 (BB*AA*4)                 // cls_oh start
#define OFF2 (OFF1 + BB*AA*CC)         // dist start
#define OFF3 (OFF2 + BB*AA)            // fg start

// ---------------- scratch (self-restoring: consumers reset to zero after reading) ----------------
__device__ int                g_cnt[BB*GG];        // reset by k_phaseB
__device__ unsigned long long g_ckey[BB*GG*CAP];   // never needs reset (guarded by g_cnt)
__device__ float              g_covl[BB*GG*CAP];
__device__ unsigned long long g_key[BB*AA];        // reset by k_final
__device__ float              g_norm[BB*AA];       // reset by k_final

// ---------------- phase A: sniff + output prefill + inside filter + CIoU + align ----------------
// grid: (66, BB), block 128
__global__ void k_phaseA(const float4* __restrict__ gtb,
                         const void* __restrict__ gmask,
                         const float2* __restrict__ anchors,
                         const float4* __restrict__ dec,
                         const float* __restrict__ scores,
                         const int* __restrict__ glab,
                         float* __restrict__ out) {
    __shared__ float4 sb[GG];     // gt box (poisoned if masked)
    __shared__ float4 sp[GG];     // (at1, sx, sy, w1h1)
    __shared__ int    slab[GG];
    __shared__ int    smode;
    int tid = threadIdx.x;
    int b = blockIdx.y;

    // per-block mask-dtype sniff (bool stored as uint8 / int32 / float32)
    if (tid == 0) smode = 0;
    __syncthreads();
    if (tid < 64) {
        unsigned w = ((const unsigned*)gmask)[tid];
        if (w == 0x3F800000u) atomicOr(&smode, 1);       // float32 1.0 -> word mode
        else if (w > 1u)      atomicOr(&smode, 2);       // packed bytes
    }
    __syncthreads();
    bool bytemode = (smode == 2);                        // f32 presence overrides

    if (tid < GG) {
        int bg = b * GG + tid;
        bool mv = bytemode ? (((const unsigned char*)gmask)[bg] != 0)
                           : (((const unsigned*)gmask)[bg] != 0);
        float4 bx = gtb[bg];
        float w1 = bx.z - bx.x, h1 = bx.w - bx.y;
        sp[tid] = make_float4(atanf(w1 / (h1 + EPSF)), bx.x + bx.z, bx.y + bx.w, w1 * h1);
        slab[tid] = glab[bg];
        if (!mv) bx.x = 3.0e38f;     // inside test always fails
        sb[tid] = bx;
    }
    __syncthreads();

    // fire-and-forget output prefill (overlaps with compute below):
    // cls_oh <- 0 (43 MB), fg <- 1.0 (argmax >= 0 always in reference)
    {
        int gid = (blockIdx.y * gridDim.x + blockIdx.x) * blockDim.x + tid;
        int nthr = gridDim.x * gridDim.y * blockDim.x;
        float4 z = make_float4(0.f, 0.f, 0.f, 0.f);
        float4* cls4 = (float4*)(out + OFF1);
        #pragma unroll 4
        for (int j = gid; j < (BB*AA*CC) / 4; j += nthr) cls4[j] = z;
        for (int j = gid; j < BB*AA; j += nthr) out[OFF3 + j] = 1.0f;
    }

    int a = blockIdx.x * 128 + tid;
    if (a >= AA) return;
    float2 an = anchors[a];
    float4 d = dec[(size_t)b * AA + a];          // coalesced
    float w2 = d.z - d.x, h2 = d.w - d.y;
    float at2 = atanf(w2 / (h2 + EPSF));
    const float* srow = scores + ((size_t)b * AA + a) * CC;

    // Pass 1: pure inside-test, 64-bit hit mask (no divergence, high MLP)
    unsigned long long hits = 0ULL;
    #pragma unroll
    for (int g = 0; g < GG; g++) {
        float4 bx = sb[g];
        bool in = (bx.x < an.x) & (bx.y < an.y) & (bx.z > an.x) & (bx.w > an.y);
        hits |= ((unsigned long long)in) << g;
    }

    // Pass 2: heavy math only on set bits
    while (hits) {
        int g = __ffsll((long long)hits) - 1;
        hits &= hits - 1;
        float4 bx = sb[g];
        float4 pp = sp[g];
        float xx1 = fmaxf(bx.x, d.x), yy1 = fmaxf(bx.y, d.y);
        float xx2 = fminf(bx.z, d.z), yy2 = fminf(bx.w, d.w);
        float inter = fmaxf(xx2 - xx1, 0.0f) * fmaxf(yy2 - yy1, 0.0f);
        float uni = pp.w + w2 * h2 - inter;
        float iou = inter / (uni + EPSF);
        float cw = fmaxf(bx.z, d.z) - fminf(bx.x, d.x);
        float ch = fmaxf(bx.w, d.w) - fminf(bx.y, d.y);
        float c2 = cw * cw + ch * ch + EPSF;
        float dx = pp.y - d.x - d.z, dy = pp.z - d.y - d.w;
        float rho2 = (dx * dx + dy * dy) * 0.25f;
        float dv = pp.x - at2;
        float v = CPI * dv * dv;
        float aco = v / (v - iou + 1.0f + EPSF);
        float ciou = iou - (rho2 / c2 + v * aco);
        if (ciou <= 0.0f) continue;
        float s = srow[slab[g]];
        float p3 = ciou * ciou * ciou;
        float alval = sqrtf(s) * p3 * p3;          // s^0.5 * relu(ciou)^6
        if (alval <= 0.0f) continue;
        int bg = b * GG + g;
        int pos = atomicAdd(&g_cnt[bg], 1);
        if (pos < CAP) {
            g_ckey[bg * CAP + pos] = ((unsigned long long)__float_as_uint(alval) << 32)
                                   | (unsigned long long)(0xFFFFFFFFu - (unsigned)a);
            g_covl[bg * CAP + pos] = ciou;
        }
    }
}

// ---------------- phase B: register-resident warp top-K + scatter ----------------
// one warp per (b,g); keys unique (anchor id embedded) -> equality-predicated selection
__global__ void k_phaseB() {
    int wid = (blockIdx.x * blockDim.x + threadIdx.x) >> 5;
    if (wid >= BB*GG) return;
    int lane = threadIdx.x & 31;
    int b = wid / GG, g = wid % GG;
    int n = g_cnt[wid];
    if (lane == 0) g_cnt[wid] = 0;     // self-restore for next replay
    if (n > CAP) n = CAP;
    if (n == 0) return;

    const unsigned long long* ck = g_ckey + (size_t)wid * CAP;
    const float*              co = g_covl + (size_t)wid * CAP;

    // 32 independent predicated loads, issued up-front (fixed unroll, register-resident)
    unsigned long long kk[16]; float oo[16];
    #pragma unroll
    for (int j = 0; j < 16; j++) {
        int idx = lane + j * 32;
        bool p = idx < n;
        kk[j] = p ? ck[idx] : 0ULL;
        oo[j] = p ? co[idx] : 0.0f;
    }

    float sel_v = 0.0f, sel_o = 0.0f; int sel_a = -1;
    int nsel = 0;
    for (int k = 0; k < KK; k++) {
        unsigned long long lb = kk[0];
        #pragma unroll
        for (int j = 1; j < 16; j++) lb = (kk[j] > lb) ? kk[j] : lb;
        unsigned long long wkey = lb;
        #pragma unroll
        for (int off = 16; off; off >>= 1) {
            unsigned long long t = __shfl_xor_sync(0xFFFFFFFFu, wkey, off);
            if (t > wkey) wkey = t;
        }
        if (wkey == 0ULL) break;
        // winner ciou + removal via equality (no indexing; keys unique, ciou>0 always)
        float cand = 0.0f;
        #pragma unroll
        for (int j = 0; j < 16; j++) {
            bool eq = (kk[j] == wkey);
            cand = eq ? oo[j] : cand;
            kk[j] = eq ? 0ULL : kk[j];
        }
        unsigned bal = __ballot_sync(0xFFFFFFFFu, cand > 0.0f);
        float wo = __shfl_sync(0xFFFFFFFFu, cand, __ffs(bal) - 1);
        if (lane == k) {
            sel_v = __uint_as_float((unsigned)(wkey >> 32));
            sel_a = (int)(0xFFFFFFFFu - (unsigned)(wkey & 0xFFFFFFFFull));
            sel_o = wo;
        }
        nsel = k + 1;
    }
    if (nsel == 0) return;

    float max_align = __shfl_sync(0xFFFFFFFFu, sel_v, 0);   // round-0 winner = largest align
    float mo = (lane < nsel) ? sel_o : 0.0f;
    #pragma unroll
    for (int off = 16; off; off >>= 1)
        mo = fmaxf(mo, __shfl_xor_sync(0xFFFFFFFFu, mo, off));

    if (lane < nsel) {
        float nc = sel_v * mo / (max_align + EPSF);
        atomicMax((int*)&g_norm[b * AA + sel_a], __float_as_int(nc));
        unsigned long long mk = ((unsigned long long)__float_as_uint(sel_o) << 32)
                              | (unsigned long long)(0xFFFFFFFFu - (unsigned)g);
        atomicMax(&g_key[b * AA + sel_a], mk);
    }
}

// ---------------- finalize: one thread per anchor; resets g_key/g_norm ----------------
__global__ void k_final(float* __restrict__ out,
                        const float4* __restrict__ gtb,
                        const int* __restrict__ glab,
                        const float* __restrict__ gdist) {
    int i = blockIdx.x * blockDim.x + threadIdx.x;
    if (i >= BB*AA) return;
    unsigned long long key = g_key[i];      // coalesced
    float nv = g_norm[i];                   // coalesced
    g_key[i] = 0ULL;                        // self-restore for next replay
    g_norm[i] = 0.0f;
    int b = i / AA;
    bool matched = (key != 0ULL);
    int g = matched ? (int)(0xFFFFFFFFu - (unsigned)(key & 0xFFFFFFFFull)) : 0;

    float4 bb = make_float4(-1.f, -1.f, -1.f, -1.f);
    float gd = -1.0f;
    if (matched) { bb = gtb[b * GG + g]; gd = gdist[b * GG + g]; }   // 1K tables, L1-hot
    ((float4*)(out + OFF0))[i] = bb;
    out[OFF2 + i] = gd * nv;                // unmatched: -1*0 = -0.0 == reference
    if (matched)
        out[OFF1 + (size_t)i * CC + glab[b * GG + g]] = nv;   // single scattered 4B store
    // fg / cls_oh zeros laid down by k_phaseA prefill
}

// ---------------- launch ----------------
extern "C" void kernel_launch(void* const* d_in, const int* in_sizes, int n_in,
                              void* d_out, int out_size) {
    int i_scores = -1, i_dec = -1, i_anch = -1, i_gtb = -1;
    int small[3]; int nsmall = 0;
    for (int i = 0; i < n_in; i++) {
        switch (in_sizes[i]) {
            case BB*AA*CC: i_scores = i; break;
            case BB*AA*4:  i_dec    = i; break;
            case AA*2:     i_anch   = i; break;
            case BB*GG*4:  i_gtb    = i; break;
            case BB*GG:    if (nsmall < 3) small[nsmall++] = i; break;
            default: break;   // distances unused
        }
    }
    int i_glab, i_gdist, i_gmask;
    if (i_gtb == 5) { i_glab = small[0]; i_gdist = small[1]; i_gmask = small[2]; }
    else            { i_gdist = small[0]; i_glab = small[1]; i_gmask = small[2]; }

    const float*  scores  = (const float*)d_in[i_scores];
    const float4* dec     = (const float4*)d_in[i_dec];
    const float2* anchors = (const float2*)d_in[i_anch];
    const float4* gtb     = (const float4*)d_in[i_gtb];
    const int*    glab    = (const int*)d_in[i_glab];
    const float*  gdist   = (const float*)d_in[i_gdist];
    const void*   gmask   = d_in[i_gmask];
    float* out = (float*)d_out;

    k_phaseA<<<dim3((AA + 127) / 128, BB), 128>>>(gtb, gmask, anchors, dec, scores, glab, out);
    k_phaseB<<<(BB*GG) / 4, 128>>>();
    k_final<<<(BB*AA + 255) / 256, 256>>>(out, gtb, glab, gdist);
}